// round 16
// baseline (speedup 1.0000x reference)
#include <cuda_runtime.h>
#include <cuda_bf16.h>
#include <math.h>
#include <stdint.h>

#define Bsz  2048
#define Dd   512
#define Cc   128
#define Tt   151
#define ROWS 16
#define G3D  1536

// K1 GEMM geometry (mma.sync path)
#define TM   128
#define TN   192
#define NMI  16          // 2048/128
#define NNI  8           // 1536/192
#define NCH  8           // 512/64 k64 blocks
#define K1_THREADS 512
#define K1_GRID (NMI*NNI)   // 128 -> single wave
#define NST  48             // 6 products x 8 chunks
#define IMG   16384         // A split image: 128 x 64 bf16 (SW128)
#define BIMG  24576         // B split image: 192 x 64 bf16 (SW128)

// K2
#define K2_THREADS 1024
#define PKK  64
#define PNT  8              // 512/64 proj k-tiles

#define SWZ128(o) ((o) ^ ((((unsigned)(o))>>3)&0x70))

// ---------------- device scratch ----------------
__device__ float g_h[Bsz * Dd];
__device__ float g_G[129 * G3D];        // gi table incl b_ih; row 128 = zero-token
__device__ float g_GH[(size_t)Bsz * G3D];
__device__ float g_WprojP[Dd * Cc];     // [k][c]
__device__ int   g_tok[Bsz];
// pre-swizzled bf16 split images: [tile][ch][split(3)][rows x 64 k]
__device__ __nv_bfloat16 g_Ah[NMI * NCH * 3 * TM * 64];
__device__ __nv_bfloat16 g_Bw[NNI * NCH * 3 * TN * 64];

// ---------------- PTX helpers ----------------
__device__ __forceinline__ unsigned smem_u32(const void* p) {
    unsigned a;
    asm("{ .reg .u64 t; cvta.to.shared.u64 t, %1; cvt.u32.u64 %0, t; }" : "=r"(a) : "l"(p));
    return a;
}
__device__ __forceinline__ unsigned long long dup2(float w) {
    unsigned long long r;
    asm("mov.b64 %0, {%1, %1};" : "=l"(r) : "f"(w));
    return r;
}
#define FMA2(c, a, b) asm("fma.rn.f32x2 %0, %1, %2, %0;" : "+l"(c) : "l"(a), "l"(b))
__device__ __forceinline__ void unpk(unsigned long long v, float& lo, float& hi) {
    asm("mov.b64 {%0, %1}, %2;" : "=f"(lo), "=f"(hi) : "l"(v));
}
__device__ __forceinline__ unsigned long long lds64(unsigned addr) {
    unsigned long long v;
    asm volatile("ld.shared.b64 %0, [%1];" : "=l"(v) : "r"(addr));
    return v;
}
__device__ __forceinline__ float ldsf(unsigned addr) {
    float v; asm volatile("ld.shared.f32 %0, [%1];" : "=f"(v) : "r"(addr)); return v;
}
__device__ __forceinline__ void cp16(unsigned dst, const void* src) {
    asm volatile("cp.async.cg.shared.global [%0], [%1], 16;" :: "r"(dst), "l"(src));
}
#define CP_COMMIT() asm volatile("cp.async.commit_group;")
#define CP_WAIT0()  asm volatile("cp.async.wait_group 0;" ::: "memory")

__device__ __forceinline__ void ldm4(uint32_t& r0, uint32_t& r1, uint32_t& r2, uint32_t& r3,
                                     unsigned addr) {
    asm volatile("ldmatrix.sync.aligned.m8n8.x4.shared.b16 {%0,%1,%2,%3}, [%4];"
                 : "=r"(r0), "=r"(r1), "=r"(r2), "=r"(r3) : "r"(addr));
}
__device__ __forceinline__ void mma16816(float* d, const uint32_t* a, const uint32_t* b) {
    asm volatile(
        "mma.sync.aligned.m16n8k16.row.col.f32.bf16.bf16.f32 "
        "{%0,%1,%2,%3}, {%4,%5,%6,%7}, {%8,%9}, {%0,%1,%2,%3};"
        : "+f"(d[0]), "+f"(d[1]), "+f"(d[2]), "+f"(d[3])
        : "r"(a[0]), "r"(a[1]), "r"(a[2]), "r"(a[3]), "r"(b[0]), "r"(b[1]));
}

__device__ __forceinline__ void split3(float x, __nv_bfloat16& b1, __nv_bfloat16& b2, __nv_bfloat16& b3) {
    b1 = __float2bfloat16(x);
    float r = x - __bfloat162float(b1);
    b2 = __float2bfloat16(r);
    r -= __bfloat162float(b2);
    b3 = __float2bfloat16(r);
}

// ---------------- setup ----------------
__global__ void setup_kernel(const float* __restrict__ feat,
                             const float* __restrict__ W_hh,
                             const float* __restrict__ W_proj)
{
    int i = blockIdx.x * blockDim.x + threadIdx.x;
    if (i < Bsz * Dd) {
        float v = feat[i];
        g_h[i] = v;
        int row = i >> 9, k = i & 511;
        int mi = row >> 7, r = row & 127, ch = k >> 6, kk = k & 63;
        char* bb = (char*)g_Ah + (size_t)(mi * NCH + ch) * 3 * IMG + SWZ128(r * 128 + kk * 2);
        __nv_bfloat16 b1, b2, b3;
        split3(v, b1, b2, b3);
        *(__nv_bfloat16*)(bb)           = b1;
        *(__nv_bfloat16*)(bb + IMG)     = b2;
        *(__nv_bfloat16*)(bb + 2 * IMG) = b3;
    }
    if (i < G3D * Dd) {
        int jj = i >> 9, k = i & 511;
        float v = W_hh[i];
        int ni = jj / TN, n = jj % TN, ch = k >> 6, kk = k & 63;
        char* bb = (char*)g_Bw + (size_t)(ni * NCH + ch) * 3 * BIMG + SWZ128(n * 128 + kk * 2);
        __nv_bfloat16 b1, b2, b3;
        split3(v, b1, b2, b3);
        *(__nv_bfloat16*)(bb)            = b1;
        *(__nv_bfloat16*)(bb + BIMG)     = b2;
        *(__nv_bfloat16*)(bb + 2 * BIMG) = b3;
    }
    if (i < Dd * Cc) { int k = i / Cc, c = i - k * Cc; g_WprojP[i] = W_proj[c * Dd + k]; }
    if (i < Bsz) g_tok[i] = 128;
}

__global__ void gi_table_kernel(const float* __restrict__ embed,
                                const float* __restrict__ W_ih,
                                const float* __restrict__ b_ih)
{
    int i = blockIdx.x * blockDim.x + threadIdx.x;
    if (i >= 129 * G3D) return;
    int c = i / G3D, j = i - c * G3D;
    float s = b_ih[j];
    if (c < Cc) {
        const float* e = embed + c * Dd;
        const float* w = W_ih + j * Dd;
        float acc = 0.f;
        #pragma unroll 4
        for (int k = 0; k < Dd; k++) acc = fmaf(e[k], w[k], acc);
        s += acc;
    }
    g_G[i] = s;
}

// ---------------- K1: GH = h @ W_hh^T (mma.sync bf16, 3-split x 6 products) ----------------
__constant__ int c_pa[6] = {0,0,0,1,1,2};
__constant__ int c_pb[6] = {2,1,0,0,1,0};
__constant__ int c_ac[6] = {0,0,0,1,1,0};   // A consume buf ^ p
__constant__ int c_bc[6] = {0,1,0,0,1,0};   // B consume buf ^ p
__constant__ int c_al[6] = {1,0,0,1,0,1};   // A load happens at this ps
__constant__ int c_bl[6] = {1,1,1,0,0,0};   // B load happens at this ps

// smem: A0 @0, A1 @16384, B0 @32768, B1 @57344
#define K1_SMEM 81920

__global__ void __launch_bounds__(K1_THREADS, 1)
gemm_kernel()
{
    extern __shared__ char smc[];
    const unsigned base = smem_u32(smc);
    const int tid  = threadIdx.x;
    const int wid  = tid >> 5;
    const int lane = tid & 31;
    const int mi   = blockIdx.x >> 3;
    const int ni   = blockIdx.x & 7;
    const int wm   = wid & 3;        // m quarter (32 rows)
    const int wn   = wid >> 2;       // n slice (48 cols)

    float acc[48];
    #pragma unroll
    for (int q = 0; q < 48; q++) acc[q] = 0.f;

    const char* Abase = (const char*)g_Ah + (size_t)mi * NCH * 3 * IMG;
    const char* Bbase = (const char*)g_Bw + (size_t)ni * NCH * 3 * BIMG;

    const int arow15 = lane & 15;
    const int aseg   = (lane >> 4) * 16;
    const int brow   = (lane & 7) + ((lane & 16) ? 8 : 0);
    const int bseg   = (lane & 8) ? 16 : 0;

    // prologue: loads for stage 0
    {
        const char* sA = Abase + (size_t)c_pa[0] * IMG;
        const char* sB = Bbase + (size_t)c_pb[0] * BIMG;
        #pragma unroll
        for (int i = 0; i < 2; i++) cp16(base + (i * 512 + tid) * 16, sA + (i * 512 + tid) * 16);
        #pragma unroll
        for (int i = 0; i < 3; i++) cp16(base + 32768u + (i * 512 + tid) * 16, sB + (i * 512 + tid) * 16);
        CP_COMMIT();
    }

    for (int s = 0; s < NST; s++) {
        CP_WAIT0();
        __syncthreads();

        if (s + 1 < NST) {
            const int t1 = s + 1, ch1 = t1 / 6, ps1 = t1 % 6, p1 = ch1 & 1;
            if (c_al[ps1]) {
                const char* sA = Abase + (size_t)(ch1 * 3 + c_pa[ps1]) * IMG;
                unsigned dst = base + (unsigned)(c_ac[ps1] ^ p1) * 16384u;
                #pragma unroll
                for (int i = 0; i < 2; i++) cp16(dst + (i * 512 + tid) * 16, sA + (i * 512 + tid) * 16);
            }
            if (c_bl[ps1]) {
                const char* sB = Bbase + (size_t)(ch1 * 3 + c_pb[ps1]) * BIMG;
                unsigned dst = base + 32768u + (unsigned)(c_bc[ps1] ^ p1) * 24576u;
                #pragma unroll
                for (int i = 0; i < 3; i++) cp16(dst + (i * 512 + tid) * 16, sB + (i * 512 + tid) * 16);
            }
            CP_COMMIT();
        }

        const int ch = s / 6, ps = s % 6, p = ch & 1;
        const unsigned sa = base + (unsigned)(c_ac[ps] ^ p) * 16384u;
        const unsigned sb = base + 32768u + (unsigned)(c_bc[ps] ^ p) * 24576u;

        #pragma unroll
        for (int ks = 0; ks < 4; ks++) {
            uint32_t af[2][4];
            #pragma unroll
            for (int mt = 0; mt < 2; mt++) {
                int row = wm * 32 + mt * 16 + arow15;
                unsigned addr = sa + SWZ128((unsigned)(row * 128 + ks * 32 + aseg));
                ldm4(af[mt][0], af[mt][1], af[mt][2], af[mt][3], addr);
            }
            uint32_t bf[6][2];
            #pragma unroll
            for (int ntp = 0; ntp < 3; ntp++) {
                int row = wn * 48 + ntp * 16 + brow;
                unsigned addr = sb + SWZ128((unsigned)(row * 128 + ks * 32 + bseg));
                uint32_t r0, r1, r2, r3;
                ldm4(r0, r1, r2, r3, addr);
                bf[2 * ntp][0] = r0;     bf[2 * ntp][1] = r1;
                bf[2 * ntp + 1][0] = r2; bf[2 * ntp + 1][1] = r3;
            }
            #pragma unroll
            for (int mt = 0; mt < 2; mt++)
                #pragma unroll
                for (int nt = 0; nt < 6; nt++)
                    mma16816(&acc[(mt * 6 + nt) * 4], af[mt], bf[nt]);
        }
    }

    // epilogue: acc -> g_GH (row-major [2048][1536])
    {
        const int r4 = lane >> 2;
        const int c2 = (lane & 3) * 2;
        #pragma unroll
        for (int mt = 0; mt < 2; mt++) {
            #pragma unroll
            for (int nt = 0; nt < 6; nt++) {
                const float* d = &acc[(mt * 6 + nt) * 4];
                int rowg = mi * 128 + wm * 32 + mt * 16 + r4;
                int colg = ni * 192 + wn * 48 + nt * 8 + c2;
                *(float2*)(g_GH + (size_t)rowg * G3D + colg)       = make_float2(d[0], d[1]);
                *(float2*)(g_GH + (size_t)(rowg + 8) * G3D + colg) = make_float2(d[2], d[3]);
            }
        }
    }
}

// ---------------- K2: gates + h update + split-store + proj + argmax ----------------
// smem: hT @0 (32KB), PB0 @32768 (32KB), PB1 @65536 (32KB), lg @98304 (8KB), tk @106496
#define K2_PB0 32768u
#define K2_PB1 65536u
#define K2_SMEM (106496 + 64)

__global__ void __launch_bounds__(K2_THREADS, 1)
step2_kernel(const float* __restrict__ b_hh,
             const float* __restrict__ b_proj,
             float* __restrict__ out,
             int t, int wr_tok)
{
    extern __shared__ float sm[];
    const unsigned base = smem_u32(sm);
    float* lg = sm + 98304 / 4;
    int*   tk = (int*)(sm + 106496 / 4);

    const int tid  = threadIdx.x;
    const int j    = tid & 511;
    const int rg   = tid >> 9;
    const int r0   = rg * 8;
    const int row0 = blockIdx.x * ROWS;

    // prefetch proj W tile 0 (64x128 f32 = 32KB) -> lands during the gate phase
    #pragma unroll
    for (int i = 0; i < 2; i++)
        cp16(base + K2_PB0 + (i * 1024 + tid) * 16, (const char*)g_WprojP + (i * 1024 + tid) * 16);
    CP_COMMIT();

    if (tid < ROWS) tk[tid] = g_tok[row0 + tid];
    __syncthreads();

    // ---- gates + h_new (col j, 8 rows in two hoisted groups of 4) ----
    {
        const float bhr = b_hh[j], bhz = b_hh[Dd + j], bhn = b_hh[2 * Dd + j];
        const int mi = row0 >> 7, ch = j >> 6, kk = j & 63;
        char* abase = (char*)g_Ah + (size_t)(mi * NCH + ch) * 3 * IMG;
        #pragma unroll
        for (int g = 0; g < 2; g++) {
            float gr[4], gz[4], gn[4], i0[4], i1[4], i2[4], hov[4];
            #pragma unroll
            for (int q = 0; q < 4; q++) {
                int r = r0 + g * 4 + q, rowg = row0 + r;
                const float* ghrow = g_GH + (size_t)rowg * G3D;
                gr[q] = ghrow[j];
                gz[q] = ghrow[512 + j];
                gn[q] = ghrow[1024 + j];
                const float* Gr = g_G + tk[r] * G3D + j;
                i0[q] = Gr[0];
                i1[q] = Gr[512];
                i2[q] = Gr[1024];
                hov[q] = g_h[rowg * Dd + j];
            }
            #pragma unroll
            for (int q = 0; q < 4; q++) {
                int r = r0 + g * 4 + q, rowg = row0 + r;
                float rgate = 1.f / (1.f + expf(-(i0[q] + gr[q] + bhr)));
                float zgate = 1.f / (1.f + expf(-(i1[q] + gz[q] + bhz)));
                float ngate = tanhf(i2[q] + rgate * (gn[q] + bhn));
                float hn = (1.f - zgate) * ngate + zgate * hov[q];
                g_h[rowg * Dd + j] = hn;
                sm[j * 16 + r]     = hn;            // hT for proj
                int rr = rowg & 127;
                char* bb = abase + SWZ128(rr * 128 + kk * 2);
                __nv_bfloat16 b1, b2, b3;
                split3(hn, b1, b2, b3);
                *(__nv_bfloat16*)(bb)           = b1;
                *(__nv_bfloat16*)(bb + IMG)     = b2;
                *(__nv_bfloat16*)(bb + 2 * IMG) = b3;
            }
        }
    }
    __syncthreads();    // hT complete

    // ---- projection: col c = tid&127, rows (2pg, 2pg+1); smem-pipelined W ----
    {
        const int c  = tid & (Cc - 1);
        const int pg = tid >> 7;
        unsigned long long p = 0ull;

        for (int pt = 0; pt < PNT; pt++) {
            CP_WAIT0();
            __syncthreads();
            if (pt + 1 < PNT) {
                const char* src = (const char*)(g_WprojP + (pt + 1) * PKK * Cc);
                unsigned dst = base + (((pt + 1) & 1) ? K2_PB1 : K2_PB0);
                #pragma unroll
                for (int i = 0; i < 2; i++)
                    cp16(dst + (i * 1024 + tid) * 16, src + (i * 1024 + tid) * 16);
                CP_COMMIT();
            }
            const unsigned wpb = base + ((pt & 1) ? K2_PB1 : K2_PB0) + c * 4;
            const unsigned hb  = base + (pt * PKK * 16 + 2 * pg) * 4;
            #pragma unroll
            for (int kq = 0; kq < PKK; kq++) {
                float wv = ldsf(wpb + kq * 512);
                unsigned long long w2 = dup2(wv);
                unsigned long long h2 = lds64(hb + kq * 64);
                FMA2(p, h2, w2);
            }
        }

        float v0, v1;
        unpk(p, v0, v1);
        const float bp = b_proj[c];
        v0 += bp; v1 += bp;
        int rowA = 2 * pg, rowB = 2 * pg + 1;
        lg[rowA * Cc + c] = v0;
        lg[rowB * Cc + c] = v1;
        out[(size_t)(row0 + rowA) * Cc * Tt + (size_t)c * Tt + t] = v0;
        out[(size_t)(row0 + rowB) * Cc * Tt + (size_t)c * Tt + t] = v1;
    }
    __syncthreads();

    // ---- argmax (first-max tie-break) ----
    if (tid < ROWS) {
        float best = lg[tid * Cc];
        int   bidx = 0;
        #pragma unroll 4
        for (int cq = 1; cq < Cc; cq++) {
            float v = lg[tid * Cc + cq];
            if (v > best) { best = v; bidx = cq; }
        }
        g_tok[row0 + tid] = bidx;
        if (wr_tok)
            out[(size_t)Bsz * Cc * Tt + (size_t)(row0 + tid) * Tt + t] = (float)bidx;
    }
}

// ---------------- launch ----------------
extern "C" void kernel_launch(void* const* d_in, const int* in_sizes, int n_in,
                              void* d_out, int out_size)
{
    const float* feat   = (const float*)d_in[0];
    const float* W_ih   = (const float*)d_in[1];
    const float* W_hh   = (const float*)d_in[2];
    const float* b_ih   = (const float*)d_in[3];
    const float* b_hh   = (const float*)d_in[4];
    const float* W_proj = (const float*)d_in[5];
    const float* b_proj = (const float*)d_in[6];
    const float* embed  = (const float*)d_in[7];
    float* out = (float*)d_out;

    int wr_tok = (out_size >= Bsz * Cc * Tt + Bsz * Tt) ? 1 : 0;

    cudaFuncSetAttribute(gemm_kernel,  cudaFuncAttributeMaxDynamicSharedMemorySize, K1_SMEM);
    cudaFuncSetAttribute(step2_kernel, cudaFuncAttributeMaxDynamicSharedMemorySize, K2_SMEM);

    setup_kernel<<<(Bsz * Dd + 255) / 256, 256>>>(feat, W_hh, W_proj);
    gi_table_kernel<<<(129 * G3D + 127) / 128, 128>>>(embed, W_ih, b_ih);

    for (int t = 0; t < Tt; t++) {
        gemm_kernel<<<K1_GRID, K1_THREADS, K1_SMEM>>>();
        step2_kernel<<<Bsz / ROWS, K2_THREADS, K2_SMEM>>>(b_hh, b_proj, out, t, wr_tok);
    }
}

// round 17
// speedup vs baseline: 1.1092x; 1.1092x over previous
#include <cuda_runtime.h>
#include <cuda_bf16.h>
#include <math.h>
#include <stdint.h>

#define Bsz  2048
#define Dd   512
#define Cc   128
#define Tt   151
#define ROWS 16
#define G3D  1536

// K1 GEMM geometry (mma.sync path)
#define TM   128
#define TN   192
#define NMI  16          // 2048/128
#define NNI  8           // 1536/192
#define NCH  8           // 512/64 k64 chunks
#define K1_THREADS 256
#define K1_GRID (NMI*NNI)   // 128 -> single wave
#define NST  24             // 6 products x 4 chunk-pairs (k128 stages)
#define IMG   16384         // A split image: 128 x 64 bf16 (SW128)
#define BIMG  24576         // B split image: 192 x 64 bf16 (SW128)

// K2
#define K2_THREADS 1024
#define PKK  64
#define PNT  8              // 512/64 proj k-tiles

#define SWZ128(o) ((o) ^ ((((unsigned)(o))>>3)&0x70))

// ---------------- device scratch ----------------
__device__ float g_h[Bsz * Dd];
__device__ float g_G[129 * G3D];        // gi table incl b_ih; row 128 = zero-token
__device__ float g_GH[(size_t)Bsz * G3D];
__device__ float g_WprojP[Dd * Cc];     // [k][c]
__device__ int   g_tok[Bsz];
// pre-swizzled bf16 split images: [tile][ch][split(3)][rows x 64 k]
__device__ __nv_bfloat16 g_Ah[NMI * NCH * 3 * TM * 64];
__device__ __nv_bfloat16 g_Bw[NNI * NCH * 3 * TN * 64];

// ---------------- PTX helpers ----------------
__device__ __forceinline__ unsigned smem_u32(const void* p) {
    unsigned a;
    asm("{ .reg .u64 t; cvta.to.shared.u64 t, %1; cvt.u32.u64 %0, t; }" : "=r"(a) : "l"(p));
    return a;
}
__device__ __forceinline__ unsigned long long dup2(float w) {
    unsigned long long r;
    asm("mov.b64 %0, {%1, %1};" : "=l"(r) : "f"(w));
    return r;
}
#define FMA2(c, a, b) asm("fma.rn.f32x2 %0, %1, %2, %0;" : "+l"(c) : "l"(a), "l"(b))
__device__ __forceinline__ void unpk(unsigned long long v, float& lo, float& hi) {
    asm("mov.b64 {%0, %1}, %2;" : "=f"(lo), "=f"(hi) : "l"(v));
}
__device__ __forceinline__ unsigned long long lds64(unsigned addr) {
    unsigned long long v;
    asm volatile("ld.shared.b64 %0, [%1];" : "=l"(v) : "r"(addr));
    return v;
}
__device__ __forceinline__ float ldsf(unsigned addr) {
    float v; asm volatile("ld.shared.f32 %0, [%1];" : "=f"(v) : "r"(addr)); return v;
}
__device__ __forceinline__ void cp16(unsigned dst, const void* src) {
    asm volatile("cp.async.cg.shared.global [%0], [%1], 16;" :: "r"(dst), "l"(src));
}
#define CP_COMMIT() asm volatile("cp.async.commit_group;")
#define CP_WAIT0()  asm volatile("cp.async.wait_group 0;" ::: "memory")

__device__ __forceinline__ void ldm4(uint32_t& r0, uint32_t& r1, uint32_t& r2, uint32_t& r3,
                                     unsigned addr) {
    asm volatile("ldmatrix.sync.aligned.m8n8.x4.shared.b16 {%0,%1,%2,%3}, [%4];"
                 : "=r"(r0), "=r"(r1), "=r"(r2), "=r"(r3) : "r"(addr));
}
__device__ __forceinline__ void mma16816(float* d, const uint32_t* a, const uint32_t* b) {
    asm volatile(
        "mma.sync.aligned.m16n8k16.row.col.f32.bf16.bf16.f32 "
        "{%0,%1,%2,%3}, {%4,%5,%6,%7}, {%8,%9}, {%0,%1,%2,%3};"
        : "+f"(d[0]), "+f"(d[1]), "+f"(d[2]), "+f"(d[3])
        : "r"(a[0]), "r"(a[1]), "r"(a[2]), "r"(a[3]), "r"(b[0]), "r"(b[1]));
}

__device__ __forceinline__ void split3(float x, __nv_bfloat16& b1, __nv_bfloat16& b2, __nv_bfloat16& b3) {
    b1 = __float2bfloat16(x);
    float r = x - __bfloat162float(b1);
    b2 = __float2bfloat16(r);
    r -= __bfloat162float(b2);
    b3 = __float2bfloat16(r);
}

// ---------------- setup ----------------
__global__ void setup_kernel(const float* __restrict__ feat,
                             const float* __restrict__ W_hh,
                             const float* __restrict__ W_proj)
{
    int i = blockIdx.x * blockDim.x + threadIdx.x;
    if (i < Bsz * Dd) {
        float v = feat[i];
        g_h[i] = v;
        int row = i >> 9, k = i & 511;
        int mi = row >> 7, r = row & 127, ch = k >> 6, kk = k & 63;
        char* bb = (char*)g_Ah + (size_t)(mi * NCH + ch) * 3 * IMG + SWZ128(r * 128 + kk * 2);
        __nv_bfloat16 b1, b2, b3;
        split3(v, b1, b2, b3);
        *(__nv_bfloat16*)(bb)           = b1;
        *(__nv_bfloat16*)(bb + IMG)     = b2;
        *(__nv_bfloat16*)(bb + 2 * IMG) = b3;
    }
    if (i < G3D * Dd) {
        int jj = i >> 9, k = i & 511;
        float v = W_hh[i];
        int ni = jj / TN, n = jj % TN, ch = k >> 6, kk = k & 63;
        char* bb = (char*)g_Bw + (size_t)(ni * NCH + ch) * 3 * BIMG + SWZ128(n * 128 + kk * 2);
        __nv_bfloat16 b1, b2, b3;
        split3(v, b1, b2, b3);
        *(__nv_bfloat16*)(bb)            = b1;
        *(__nv_bfloat16*)(bb + BIMG)     = b2;
        *(__nv_bfloat16*)(bb + 2 * BIMG) = b3;
    }
    if (i < Dd * Cc) { int k = i / Cc, c = i - k * Cc; g_WprojP[i] = W_proj[c * Dd + k]; }
    if (i < Bsz) g_tok[i] = 128;
}

__global__ void gi_table_kernel(const float* __restrict__ embed,
                                const float* __restrict__ W_ih,
                                const float* __restrict__ b_ih)
{
    int i = blockIdx.x * blockDim.x + threadIdx.x;
    if (i >= 129 * G3D) return;
    int c = i / G3D, j = i - c * G3D;
    float s = b_ih[j];
    if (c < Cc) {
        const float* e = embed + c * Dd;
        const float* w = W_ih + j * Dd;
        float acc = 0.f;
        #pragma unroll 4
        for (int k = 0; k < Dd; k++) acc = fmaf(e[k], w[k], acc);
        s += acc;
    }
    g_G[i] = s;
}

// ---------------- K1: GH = h @ W_hh^T (mma.sync bf16, 3-split x 6 products, k128 stages) ----------------
__constant__ int c_pa[6] = {0,0,0,1,1,2};
__constant__ int c_pb[6] = {2,1,0,0,1,0};
__constant__ int c_ac[6] = {0,0,0,1,1,0};   // A consume buf ^ p
__constant__ int c_bc[6] = {0,1,0,0,1,0};   // B consume buf ^ p
__constant__ int c_al[6] = {1,0,0,1,0,1};   // A load happens at this ps
__constant__ int c_bl[6] = {1,1,1,0,0,0};   // B load happens at this ps

// smem: A0 @0 (32KB = 2x16KB sub-images), A1 @32768, B0 @65536 (48KB), B1 @114688
#define K1_SMEM 163840

__global__ void __launch_bounds__(K1_THREADS, 1)
gemm_kernel()
{
    extern __shared__ char smc[];
    const unsigned base = smem_u32(smc);
    const int tid  = threadIdx.x;
    const int wid  = tid >> 5;
    const int lane = tid & 31;
    const int mi   = blockIdx.x >> 3;
    const int ni   = blockIdx.x & 7;
    const int wm   = wid & 1;        // m half (64 rows)
    const int wn   = wid >> 1;       // n slice (48 cols)

    float acc[96];
    #pragma unroll
    for (int q = 0; q < 96; q++) acc[q] = 0.f;

    const char* Abase = (const char*)g_Ah + (size_t)mi * NCH * 3 * IMG;
    const char* Bbase = (const char*)g_Bw + (size_t)ni * NCH * 3 * BIMG;

    const int arow15 = lane & 15;
    const int aseg   = (lane >> 4) * 16;
    const int brow   = (lane & 7) + ((lane & 16) ? 8 : 0);
    const int bseg   = (lane & 8) ? 16 : 0;

    // prologue: loads for stage 0 (cp=0, ps=0): A split 0 of ch{0,1}; B split 2 of ch{0,1}
    {
        #pragma unroll
        for (int sub = 0; sub < 2; sub++) {
            const char* sA = Abase + (size_t)(sub * 3 + c_pa[0]) * IMG;
            const char* sB = Bbase + (size_t)(sub * 3 + c_pb[0]) * BIMG;
            unsigned dA = base + sub * 16384u;
            unsigned dB = base + 65536u + sub * 24576u;
            #pragma unroll
            for (int i = 0; i < 4; i++) cp16(dA + (i * 256 + tid) * 16, sA + (i * 256 + tid) * 16);
            #pragma unroll
            for (int i = 0; i < 6; i++) cp16(dB + (i * 256 + tid) * 16, sB + (i * 256 + tid) * 16);
        }
        CP_COMMIT();
    }

    for (int s = 0; s < NST; s++) {
        CP_WAIT0();
        __syncthreads();

        if (s + 1 < NST) {
            const int t1 = s + 1, cp1 = t1 / 6, ps1 = t1 % 6, p1 = cp1 & 1;
            if (c_al[ps1]) {
                unsigned dst = base + (unsigned)(c_ac[ps1] ^ p1) * 32768u;
                #pragma unroll
                for (int sub = 0; sub < 2; sub++) {
                    const char* sA = Abase + (size_t)((2 * cp1 + sub) * 3 + c_pa[ps1]) * IMG;
                    #pragma unroll
                    for (int i = 0; i < 4; i++)
                        cp16(dst + sub * 16384u + (i * 256 + tid) * 16, sA + (i * 256 + tid) * 16);
                }
            }
            if (c_bl[ps1]) {
                unsigned dst = base + 65536u + (unsigned)(c_bc[ps1] ^ p1) * 49152u;
                #pragma unroll
                for (int sub = 0; sub < 2; sub++) {
                    const char* sB = Bbase + (size_t)((2 * cp1 + sub) * 3 + c_pb[ps1]) * BIMG;
                    #pragma unroll
                    for (int i = 0; i < 6; i++)
                        cp16(dst + sub * 24576u + (i * 256 + tid) * 16, sB + (i * 256 + tid) * 16);
                }
            }
            CP_COMMIT();
        }

        const int ps = s % 6, p = (s / 6) & 1;
        const unsigned sa0 = base + (unsigned)(c_ac[ps] ^ p) * 32768u;
        const unsigned sb0 = base + 65536u + (unsigned)(c_bc[ps] ^ p) * 49152u;

        #pragma unroll
        for (int sub = 0; sub < 2; sub++) {
            const unsigned sa = sa0 + sub * 16384u;
            const unsigned sb = sb0 + sub * 24576u;
            #pragma unroll
            for (int ks = 0; ks < 4; ks++) {
                uint32_t af[4][4];
                #pragma unroll
                for (int mt = 0; mt < 4; mt++) {
                    int row = wm * 64 + mt * 16 + arow15;
                    unsigned addr = sa + SWZ128((unsigned)(row * 128 + ks * 32 + aseg));
                    ldm4(af[mt][0], af[mt][1], af[mt][2], af[mt][3], addr);
                }
                uint32_t bf[6][2];
                #pragma unroll
                for (int ntp = 0; ntp < 3; ntp++) {
                    int row = wn * 48 + ntp * 16 + brow;
                    unsigned addr = sb + SWZ128((unsigned)(row * 128 + ks * 32 + bseg));
                    uint32_t r0, r1, r2, r3;
                    ldm4(r0, r1, r2, r3, addr);
                    bf[2 * ntp][0] = r0;     bf[2 * ntp][1] = r1;
                    bf[2 * ntp + 1][0] = r2; bf[2 * ntp + 1][1] = r3;
                }
                #pragma unroll
                for (int mt = 0; mt < 4; mt++)
                    #pragma unroll
                    for (int nt = 0; nt < 6; nt++)
                        mma16816(&acc[(mt * 6 + nt) * 4], af[mt], bf[nt]);
            }
        }
    }

    // epilogue: acc -> g_GH (row-major [2048][1536])
    {
        const int r4 = lane >> 2;
        const int c2 = (lane & 3) * 2;
        #pragma unroll
        for (int mt = 0; mt < 4; mt++) {
            #pragma unroll
            for (int nt = 0; nt < 6; nt++) {
                const float* d = &acc[(mt * 6 + nt) * 4];
                int rowg = mi * 128 + wm * 64 + mt * 16 + r4;
                int colg = ni * 192 + wn * 48 + nt * 8 + c2;
                *(float2*)(g_GH + (size_t)rowg * G3D + colg)       = make_float2(d[0], d[1]);
                *(float2*)(g_GH + (size_t)(rowg + 8) * G3D + colg) = make_float2(d[2], d[3]);
            }
        }
    }
}

// ---------------- K2: gates + h update + split-store + proj + argmax ----------------
// smem: hT @0 (32KB), PB0 @32768 (32KB), PB1 @65536 (32KB), lg @98304 (8KB), tk @106496
#define K2_PB0 32768u
#define K2_PB1 65536u
#define K2_SMEM (106496 + 64)

__global__ void __launch_bounds__(K2_THREADS, 1)
step2_kernel(const float* __restrict__ b_hh,
             const float* __restrict__ b_proj,
             float* __restrict__ out,
             int t, int wr_tok)
{
    extern __shared__ float sm[];
    const unsigned base = smem_u32(sm);
    float* lg = sm + 98304 / 4;
    int*   tk = (int*)(sm + 106496 / 4);

    const int tid  = threadIdx.x;
    const int j    = tid & 511;
    const int rg   = tid >> 9;
    const int r0   = rg * 8;
    const int row0 = blockIdx.x * ROWS;

    // prefetch proj W tile 0 (64x128 f32 = 32KB) -> lands during the gate phase
    #pragma unroll
    for (int i = 0; i < 2; i++)
        cp16(base + K2_PB0 + (i * 1024 + tid) * 16, (const char*)g_WprojP + (i * 1024 + tid) * 16);
    CP_COMMIT();

    if (tid < ROWS) tk[tid] = g_tok[row0 + tid];
    __syncthreads();

    // ---- gates + h_new (col j, 8 rows in two hoisted groups of 4) ----
    {
        const float bhr = b_hh[j], bhz = b_hh[Dd + j], bhn = b_hh[2 * Dd + j];
        const int mi = row0 >> 7, ch = j >> 6, kk = j & 63;
        char* abase = (char*)g_Ah + (size_t)(mi * NCH + ch) * 3 * IMG;
        #pragma unroll
        for (int g = 0; g < 2; g++) {
            float gr[4], gz[4], gn[4], i0[4], i1[4], i2[4], hov[4];
            #pragma unroll
            for (int q = 0; q < 4; q++) {
                int r = r0 + g * 4 + q, rowg = row0 + r;
                const float* ghrow = g_GH + (size_t)rowg * G3D;
                gr[q] = ghrow[j];
                gz[q] = ghrow[512 + j];
                gn[q] = ghrow[1024 + j];
                const float* Gr = g_G + tk[r] * G3D + j;
                i0[q] = Gr[0];
                i1[q] = Gr[512];
                i2[q] = Gr[1024];
                hov[q] = g_h[rowg * Dd + j];
            }
            #pragma unroll
            for (int q = 0; q < 4; q++) {
                int r = r0 + g * 4 + q, rowg = row0 + r;
                float rgate = 1.f / (1.f + expf(-(i0[q] + gr[q] + bhr)));
                float zgate = 1.f / (1.f + expf(-(i1[q] + gz[q] + bhz)));
                float ngate = tanhf(i2[q] + rgate * (gn[q] + bhn));
                float hn = (1.f - zgate) * ngate + zgate * hov[q];
                g_h[rowg * Dd + j] = hn;
                sm[j * 16 + r]     = hn;            // hT for proj
                int rr = rowg & 127;
                char* bb = abase + SWZ128(rr * 128 + kk * 2);
                __nv_bfloat16 b1, b2, b3;
                split3(hn, b1, b2, b3);
                *(__nv_bfloat16*)(bb)           = b1;
                *(__nv_bfloat16*)(bb + IMG)     = b2;
                *(__nv_bfloat16*)(bb + 2 * IMG) = b3;
            }
        }
    }
    __syncthreads();    // hT complete

    // ---- projection: col c = tid&127, rows (2pg, 2pg+1); smem-pipelined W ----
    {
        const int c  = tid & (Cc - 1);
        const int pg = tid >> 7;
        unsigned long long p = 0ull;

        for (int pt = 0; pt < PNT; pt++) {
            CP_WAIT0();
            __syncthreads();
            if (pt + 1 < PNT) {
                const char* src = (const char*)(g_WprojP + (pt + 1) * PKK * Cc);
                unsigned dst = base + (((pt + 1) & 1) ? K2_PB1 : K2_PB0);
                #pragma unroll
                for (int i = 0; i < 2; i++)
                    cp16(dst + (i * 1024 + tid) * 16, src + (i * 1024 + tid) * 16);
                CP_COMMIT();
            }
            const unsigned wpb = base + ((pt & 1) ? K2_PB1 : K2_PB0) + c * 4;
            const unsigned hb  = base + (pt * PKK * 16 + 2 * pg) * 4;
            #pragma unroll
            for (int kq = 0; kq < PKK; kq++) {
                float wv = ldsf(wpb + kq * 512);
                unsigned long long w2 = dup2(wv);
                unsigned long long h2 = lds64(hb + kq * 64);
                FMA2(p, h2, w2);
            }
        }

        float v0, v1;
        unpk(p, v0, v1);
        const float bp = b_proj[c];
        v0 += bp; v1 += bp;
        int rowA = 2 * pg, rowB = 2 * pg + 1;
        lg[rowA * Cc + c] = v0;
        lg[rowB * Cc + c] = v1;
        out[(size_t)(row0 + rowA) * Cc * Tt + (size_t)c * Tt + t] = v0;
        out[(size_t)(row0 + rowB) * Cc * Tt + (size_t)c * Tt + t] = v1;
    }
    __syncthreads();

    // ---- argmax (first-max tie-break) ----
    if (tid < ROWS) {
        float best = lg[tid * Cc];
        int   bidx = 0;
        #pragma unroll 4
        for (int cq = 1; cq < Cc; cq++) {
            float v = lg[tid * Cc + cq];
            if (v > best) { best = v; bidx = cq; }
        }
        g_tok[row0 + tid] = bidx;
        if (wr_tok)
            out[(size_t)Bsz * Cc * Tt + (size_t)(row0 + tid) * Tt + t] = (float)bidx;
    }
}

// ---------------- launch ----------------
extern "C" void kernel_launch(void* const* d_in, const int* in_sizes, int n_in,
                              void* d_out, int out_size)
{
    const float* feat   = (const float*)d_in[0];
    const float* W_ih   = (const float*)d_in[1];
    const float* W_hh   = (const float*)d_in[2];
    const float* b_ih   = (const float*)d_in[3];
    const float* b_hh   = (const float*)d_in[4];
    const float* W_proj = (const float*)d_in[5];
    const float* b_proj = (const float*)d_in[6];
    const float* embed  = (const float*)d_in[7];
    float* out = (float*)d_out;

    int wr_tok = (out_size >= Bsz * Cc * Tt + Bsz * Tt) ? 1 : 0;

    cudaFuncSetAttribute(gemm_kernel,  cudaFuncAttributeMaxDynamicSharedMemorySize, K1_SMEM);
    cudaFuncSetAttribute(step2_kernel, cudaFuncAttributeMaxDynamicSharedMemorySize, K2_SMEM);

    setup_kernel<<<(Bsz * Dd + 255) / 256, 256>>>(feat, W_hh, W_proj);
    gi_table_kernel<<<(129 * G3D + 127) / 128, 128>>>(embed, W_ih, b_ih);

    for (int t = 0; t < Tt; t++) {
        gemm_kernel<<<K1_GRID, K1_THREADS, K1_SMEM>>>();
        step2_kernel<<<Bsz / ROWS, K2_THREADS, K2_SMEM>>>(b_hh, b_proj, out, t, wr_tok);
    }
}